// round 13
// baseline (speedup 1.0000x reference)
#include <cuda_runtime.h>
#include <cuda_bf16.h>
#include <cstdint>

#define NN 16384
#define DD 256
#define BM 128
#define NTILES (NN / 128)             // 128
#define NHALF (NTILES * 2)            // 256 half-tiles of 128x64
#define TILE_BYTES (BM * DD)          // 32768 (int8)
#define THREADS 512                   // 16 warps: 4 tile-groups of 4

// A: per 128-row tile, 256B rows, 16B-chunk XOR swizzle (chunk ^ (row&7)) for ldmatrix.
// B: per 128-col tile, IMMA-fragment order: 64 blocks of 512B, block = (nf2*8+ks),
//    lane L's 16B = {b0,b1 cols lo8; b0,b1 cols hi8} for its (gq,tid_g)=(L>>2,L&3).
__device__ __align__(128) int8_t g_flB[NN * DD];  // 4 MB
__device__ __align__(128) int8_t g_fgB[NN * DD];  // 4 MB
__device__ float g_sa[NN];                        // per-row A scale (incl 1/(T*ln2))
__device__ float g_sb[NN];                        // per-col B scale
__device__ float g_bsum[NN / BM];

// ---------------------------------------------------------------------------
__device__ __forceinline__ uint32_t smem_u32(const void* p) {
    uint32_t a;
    asm("{ .reg .u64 t; cvta.to.shared.u64 t, %1; cvt.u32.u64 %0, t; }" : "=r"(a) : "l"(p));
    return a;
}
__device__ __forceinline__ float ex2f(float x) {
    float y; asm("ex2.approx.ftz.f32 %0, %1;" : "=f"(y) : "f"(x)); return y;
}
__device__ __forceinline__ float lg2f(float x) {
    float y; asm("lg2.approx.ftz.f32 %0, %1;" : "=f"(y) : "f"(x)); return y;
}

#define MBARRIER_INIT(mbar, count) \
    asm volatile("mbarrier.init.shared.b64 [%0], %1;" :: "r"((uint32_t)(mbar)), "r"((uint32_t)(count)) : "memory")
#define MBARRIER_EXPECT_TX(mbar, bytes) \
    asm volatile("mbarrier.arrive.expect_tx.shared.b64 _, [%0], %1;" :: "r"((uint32_t)(mbar)), "r"((uint32_t)(bytes)) : "memory")
#define MBARRIER_WAIT_PARITY(mbar, parity) do { \
    uint32_t _m = (uint32_t)(mbar); uint32_t _p = (uint32_t)(parity); uint32_t _d; \
    asm volatile("{\n\t.reg .pred p;\n\t" \
        "mbarrier.try_wait.parity.acquire.cta.shared::cta.b64 p, [%1], %2;\n\t" \
        "selp.b32 %0, 1, 0, p;\n\t}" : "=r"(_d) : "r"(_m), "r"(_p) : "memory"); \
    if (!_d) { \
        asm volatile("{\n\t.reg .pred P1;\n\t" \
            "WL_%=:\n\t" \
            "mbarrier.try_wait.parity.acquire.cta.shared::cta.b64 P1, [%0], %1, 0x989680;\n\t" \
            "@P1 bra.uni WD_%=;\n\t" \
            "bra.uni WL_%=;\n\t" \
            "WD_%=:\n\t}" :: "r"(_m), "r"(_p) : "memory"); \
    } \
} while (0)

__device__ __forceinline__ void bulk_copy(uint32_t dst_smem, const void* src, uint32_t bytes,
                                          uint32_t mbar) {
    asm volatile("cp.async.bulk.shared::cta.global.mbarrier::complete_tx::bytes [%0], [%1], %2, [%3];"
                 :: "r"(dst_smem), "l"(src), "r"(bytes), "r"(mbar) : "memory");
}
__device__ __forceinline__ void ldsm4(uint32_t* r, uint32_t addr) {
    asm volatile("ldmatrix.sync.aligned.m8n8.x4.shared.b16 {%0,%1,%2,%3}, [%4];"
                 : "=r"(r[0]), "=r"(r[1]), "=r"(r[2]), "=r"(r[3]) : "r"(addr));
}
__device__ __forceinline__ void mmas8(int* d, const uint32_t* a, uint32_t b0, uint32_t b1) {
    asm volatile("mma.sync.aligned.m16n8k32.row.col.s32.s8.s8.s32 "
                 "{%0,%1,%2,%3}, {%4,%5,%6,%7}, {%8,%9}, {%0,%1,%2,%3};"
                 : "+r"(d[0]), "+r"(d[1]), "+r"(d[2]), "+r"(d[3])
                 : "r"(a[0]), "r"(a[1]), "r"(a[2]), "r"(a[3]), "r"(b0), "r"(b1));
}
__device__ __forceinline__ uint32_t pack4(float a, float b, float c, float d) {
    int q0 = __float2int_rn(a), q1 = __float2int_rn(b);
    int q2 = __float2int_rn(c), q3 = __float2int_rn(d);
    return (uint32_t)(q0 & 0xff) | ((uint32_t)(q1 & 0xff) << 8) |
           ((uint32_t)(q2 & 0xff) << 16) | ((uint32_t)q3 << 24);
}

// ---------------------------------------------------------------------------
// Kernel A: L2-normalize, int8-quantize with per-row scale, pack.
// which=0: A swizzled-row layout + g_sa (incl K2). which=1: B frag layout + g_sb.
// One warp per row; lane owns k = lane*8..+7.
// ---------------------------------------------------------------------------
__global__ void __launch_bounds__(256) norm_pack_kernel(const float* __restrict__ in, int which) {
    const float K2 = (float)(1.0 / (0.07 * 0.6931471805599453));
    char* outB = (char*)(which ? g_fgB : g_flB);
    const int wid = threadIdx.x >> 5;
    const int lane = threadIdx.x & 31;
    const int row = blockIdx.x * 8 + wid;

    const float4* r4 = (const float4*)(in + (size_t)row * DD);
    float4 a = r4[2 * lane];
    float4 b = r4[2 * lane + 1];

    float ss = a.x * a.x + a.y * a.y + a.z * a.z + a.w * a.w
             + b.x * b.x + b.y * b.y + b.z * b.z + b.w * b.w;
    #pragma unroll
    for (int off = 16; off > 0; off >>= 1)
        ss += __shfl_xor_sync(0xffffffffu, ss, off);
    float s = 1.0f / fmaxf(sqrtf(ss), 1e-12f);

    float v[8] = {a.x * s, a.y * s, a.z * s, a.w * s, b.x * s, b.y * s, b.z * s, b.w * s};
    float mx = 0.0f;
    #pragma unroll
    for (int j = 0; j < 8; j++) mx = fmaxf(mx, fabsf(v[j]));
    #pragma unroll
    for (int off = 16; off > 0; off >>= 1)
        mx = fmaxf(mx, __shfl_xor_sync(0xffffffffu, mx, off));
    mx = fmaxf(mx, 1e-12f);
    const float qs = 127.0f / mx;

    uint32_t w0 = pack4(v[0] * qs, v[1] * qs, v[2] * qs, v[3] * qs);
    uint32_t w1 = pack4(v[4] * qs, v[5] * qs, v[6] * qs, v[7] * qs);

    if (lane == 0) {
        if (which) g_sb[row] = mx / 127.0f;
        else       g_sa[row] = (mx / 127.0f) * K2;
    }

    const int t = row >> 7;
    char* tbase = outB + (size_t)t * TILE_BYTES;

    if (!which) {
        // A: 256B rows, chunk c = k/16 (lane covers bytes lane*8..+7 -> chunk lane>>1)
        const int r = row & 127;
        const uint32_t c = (uint32_t)((lane >> 1) ^ (r & 7));
        uint2 p; p.x = w0; p.y = w1;
        *(uint2*)(tbase + (uint32_t)r * 256u + c * 16u + (uint32_t)(lane & 1) * 8u) = p;
    } else {
        // B fragment layout: block (nf2*8+ks)*512; element (nl,k):
        // off = ((nl&7)*4 + (k>>2)&3)*16 + (((nl>>3)&1)*2 + (k>>4)&1)*4 + (k&3)
        const int nc = row & 127;
        const int nf2 = nc >> 4;
        const int nl = nc & 15;
        const int gq = nl & 7;
        const int cg = (nl >> 3) & 1;
        const int ks = lane >> 2;                 // k-block of 32
        char* blk = tbase + (uint32_t)(nf2 * 8 + ks) * 512u;
        uint32_t wv[2] = {w0, w1};
        #pragma unroll
        for (int j = 0; j < 2; j++) {             // word j: k0 = lane*8 + j*4
            const int e = 2 * lane + j;           // k0/4
            const int tg = e & 3;                 // tid in group
            const int rg = (e >> 2) & 1;          // reg (k hi/lo 16)
            *(uint32_t*)(blk + (uint32_t)((gq * 4 + tg) * 16 + (cg * 2 + rg) * 4)) = wv[j];
        }
    }
}

// ---------------------------------------------------------------------------
__global__ void zero_bsum_kernel() {
    g_bsum[threadIdx.x] = 0.0f;
}

// ---------------------------------------------------------------------------
// Kernel B: IMMA s8 GEMM + fused LSE. 16 warps in 4 tile-groups; group handles
// half-tiles ht = 4j+g (128 rows x 64 cols). Warp tile = 64x32, k=32/step.
// ---------------------------------------------------------------------------
__global__ void __launch_bounds__(THREADS, 1) gemm_lse_kernel() {
    extern __shared__ __align__(128) char smem_raw[];
    const uint32_t sbase0 = smem_u32(smem_raw);
    const uint32_t cb = (sbase0 + 1023) & ~1023u;
    char* cptr = smem_raw + (cb - sbase0);

    const uint32_t MB_A = cb + 0;
    float* diag_s  = (float*)(cptr + 64);    // [128]
    float* red_s   = (float*)(cptr + 576);   // [128][8]
    float* sloss_s = (float*)(cptr + 4672);  // [128]
    const uint32_t A_S = cb + 8192;

    const int tid = threadIdx.x;
    const int lane = tid & 31;
    const int w = tid >> 5;
    const int g = w >> 2;                    // tile-group 0..3
    const int wl = w & 3;
    const int wm = wl >> 1;                  // M half (64 rows)
    const int wn = wl & 1;                   // 32-col half
    const int bx = blockIdx.x;

    if (tid == 0) MBARRIER_INIT(MB_A, 1);
    __syncthreads();
    if (tid == 0) {
        MBARRIER_EXPECT_TX(MB_A, TILE_BYTES);
        bulk_copy(A_S, (const char*)g_flB + (size_t)bx * TILE_BYTES, TILE_BYTES, MB_A);
    }

    // A ldmatrix addressing: 256B rows, chunk = 2*ks + kbA, swizzle ^ (lane&7)
    const uint32_t xl = (uint32_t)(lane & 7);
    const int kbA = (lane >> 4) & 1;
    const int rbA = (lane >> 3) & 1;
    uint32_t aBase[4];
    #pragma unroll
    for (int mf = 0; mf < 4; mf++)
        aBase[mf] = A_S + (uint32_t)(wm * 64 + mf * 16 + (lane & 7) + rbA * 8) * 256u;

    // Row scales (8 per thread, fixed for the whole kernel)
    const int gq = lane >> 2;
    const int qq = lane & 3;
    float sa8[4][2];
    #pragma unroll
    for (int mf = 0; mf < 4; mf++)
        #pragma unroll
        for (int h = 0; h < 2; h++)
            sa8[mf][h] = g_sa[bx * 128 + wm * 64 + mf * 16 + gq + h * 8];

    const char* __restrict__ bAll = (const char*)g_fgB;
    const uint32_t bLane = (uint32_t)lane * 16u;

    float rs[8];
    #pragma unroll
    for (int j = 0; j < 8; j++) rs[j] = 0.0f;

    MBARRIER_WAIT_PARITY(MB_A, 0);

    for (int j = 0; j < NHALF / 4; j++) {
        const int ht = 4 * j + g;
        const int i = ht >> 1;               // tile index
        const int nh = ht & 1;               // 64-col half
        const int nf2base = nh * 4 + wn * 2; // first 16-col block for this warp
        const char* __restrict__ bW = bAll + (size_t)i * TILE_BYTES
                                    + (uint32_t)(nf2base * 8) * 512u + bLane;

        int acc[4][4][4];                    // [mf][q*2+cg][h*2+cc]
        #pragma unroll
        for (int mf = 0; mf < 4; mf++)
            #pragma unroll
            for (int nf = 0; nf < 4; nf++)
                #pragma unroll
                for (int c = 0; c < 4; c++) acc[mf][nf][c] = 0;

        uint4 bf0[2], bf1[2];
        #pragma unroll
        for (int q = 0; q < 2; q++)
            bf0[q] = *(const uint4*)(bW + (uint32_t)(q * 8) * 512u);

        #pragma unroll
        for (int ks = 0; ks < 8; ks++) {
            uint4* cur = (ks & 1) ? bf1 : bf0;
            uint4* nxt = (ks & 1) ? bf0 : bf1;
            if (ks + 1 < 8) {
                #pragma unroll
                for (int q = 0; q < 2; q++)
                    nxt[q] = *(const uint4*)(bW + (uint32_t)(q * 8 + ks + 1) * 512u);
            }
            uint32_t afrag[4][4];
            const uint32_t cA = (uint32_t)((2 * ks + kbA) ^ (int)xl) << 4;
            #pragma unroll
            for (int mf = 0; mf < 4; mf++) ldsm4(afrag[mf], aBase[mf] + cA);
            #pragma unroll
            for (int mf = 0; mf < 4; mf++)
                #pragma unroll
                for (int q = 0; q < 2; q++) {
                    mmas8(acc[mf][q * 2],     afrag[mf], cur[q].x, cur[q].y);
                    mmas8(acc[mf][q * 2 + 1], afrag[mf], cur[q].z, cur[q].w);
                }
        }

        // col scales for this thread's 8 columns (cc pairs)
        const int colbase = i * 128 + nh * 64 + wn * 32 + qq * 2;
        float2 sbv[2][2];
        #pragma unroll
        for (int q = 0; q < 2; q++)
            #pragma unroll
            for (int cg = 0; cg < 2; cg++)
                sbv[q][cg] = *(const float2*)(g_sb + colbase + q * 16 + cg * 8);

        if (i == bx) {   // diagonal tile for this CTA
            #pragma unroll
            for (int mf = 0; mf < 4; mf++)
                #pragma unroll
                for (int q = 0; q < 2; q++)
                    #pragma unroll
                    for (int cg = 0; cg < 2; cg++)
                        #pragma unroll
                        for (int h = 0; h < 2; h++)
                            #pragma unroll
                            for (int cc = 0; cc < 2; cc++) {
                                int R = wm * 64 + mf * 16 + gq + h * 8;
                                int C = nh * 64 + wn * 32 + q * 16 + cg * 8 + qq * 2 + cc;
                                if (R == C) {
                                    float t = (float)acc[mf][q * 2 + cg][h * 2 + cc];
                                    float sc = cc ? sbv[q][cg].y : sbv[q][cg].x;
                                    diag_s[R] = t * sc * sa8[mf][h];
                                }
                            }
        }

        #pragma unroll
        for (int mf = 0; mf < 4; mf++)
            #pragma unroll
            for (int q = 0; q < 2; q++)
                #pragma unroll
                for (int cg = 0; cg < 2; cg++) {
                    const int nf = q * 2 + cg;
                    float t0 = (float)acc[mf][nf][0] * sbv[q][cg].x * sa8[mf][0];
                    float t1 = (float)acc[mf][nf][1] * sbv[q][cg].y * sa8[mf][0];
                    float t2 = (float)acc[mf][nf][2] * sbv[q][cg].x * sa8[mf][1];
                    float t3 = (float)acc[mf][nf][3] * sbv[q][cg].y * sa8[mf][1];
                    rs[mf * 2 + 0] += ex2f(t0) + ex2f(t1);
                    rs[mf * 2 + 1] += ex2f(t2) + ex2f(t3);
                }
    }

    // lanes l, l^1, l^2 share the same rows
    #pragma unroll
    for (int j = 0; j < 8; j++) {
        rs[j] += __shfl_xor_sync(0xffffffffu, rs[j], 1);
        rs[j] += __shfl_xor_sync(0xffffffffu, rs[j], 2);
    }
    if ((lane & 3) == 0) {
        #pragma unroll
        for (int mf = 0; mf < 4; mf++)
            #pragma unroll
            for (int h = 0; h < 2; h++) {
                int R = wm * 64 + mf * 16 + gq + h * 8;
                red_s[R * 8 + g * 2 + wn] = rs[mf * 2 + h];
            }
    }
    __syncthreads();

    if (tid < 128) {
        float tot = 0.0f;
        #pragma unroll
        for (int c = 0; c < 8; c++) tot += red_s[tid * 8 + c];
        sloss_s[tid] = 0.6931471805599453f * (lg2f(tot) - diag_s[tid]);
    }
    __syncthreads();
    if (tid == 0) {
        float t = 0.0f;
        #pragma unroll 8
        for (int r = 0; r < BM; r++) t += sloss_s[r];
        g_bsum[bx] = t;
    }
}

// ---------------------------------------------------------------------------
__global__ void finalize_kernel(float* __restrict__ out) {
    __shared__ float sh[128];
    const int t = threadIdx.x;
    sh[t] = g_bsum[t];
    __syncthreads();
    #pragma unroll
    for (int off = 64; off > 0; off >>= 1) {
        if (t < off) sh[t] += sh[t + off];
        __syncthreads();
    }
    if (t == 0) out[0] = sh[0] / (float)NN;
}

// ---------------------------------------------------------------------------
extern "C" void kernel_launch(void* const* d_in, const int* in_sizes, int n_in,
                              void* d_out, int out_size) {
    const float* feat_local  = (const float*)d_in[0];
    const float* feat_global = (const float*)d_in[1];
    float* out = (float*)d_out;

    const int smem_bytes = 1024 + 8192 + TILE_BYTES;  // ~41 KB
    static bool attr_set = false;
    if (!attr_set) {
        cudaFuncSetAttribute(gemm_lse_kernel,
                             cudaFuncAttributeMaxDynamicSharedMemorySize, smem_bytes);
        attr_set = true;
    }

    norm_pack_kernel<<<NN / 8, 256>>>(feat_local, 0);   // launch 1
    norm_pack_kernel<<<NN / 8, 256>>>(feat_global, 1);  // launch 2
    zero_bsum_kernel<<<1, 128>>>();                     // launch 3
    gemm_lse_kernel<<<NN / BM, THREADS, smem_bytes>>>();// launch 4  <- profiled
    finalize_kernel<<<1, 128>>>(out);                   // launch 5
}

// round 14
// speedup vs baseline: 2.3598x; 2.3598x over previous
#include <cuda_runtime.h>
#include <cuda_bf16.h>
#include <cstdint>

#define NN 16384
#define DD 256
#define BM 128
#define NTILES (NN / 128)             // 128
#define TILE_BYTES (BM * DD * 2)      // 65536 (bf16)
#define THREADS 512                   // 16 warps, all on one tile

// A: per 128-row tile, row-major 512B rows with 16B-chunk XOR swizzle (ldmatrix).
// B: per 128-col tile, MMA-fragment order: 128 blocks of 512B, block = (nf2*16+ks).
__device__ __align__(128) __nv_bfloat16 g_flB[NN * DD];  // 8 MB, pre-scaled by 1/(T*ln2)
__device__ __align__(128) __nv_bfloat16 g_fgB[NN * DD];  // 8 MB
__device__ float g_bsum[NN / BM];

// ---------------------------------------------------------------------------
__device__ __forceinline__ uint32_t smem_u32(const void* p) {
    uint32_t a;
    asm("{ .reg .u64 t; cvta.to.shared.u64 t, %1; cvt.u32.u64 %0, t; }" : "=r"(a) : "l"(p));
    return a;
}
__device__ __forceinline__ float ex2f(float x) {
    float y; asm("ex2.approx.ftz.f32 %0, %1;" : "=f"(y) : "f"(x)); return y;
}
__device__ __forceinline__ float lg2f(float x) {
    float y; asm("lg2.approx.ftz.f32 %0, %1;" : "=f"(y) : "f"(x)); return y;
}

#define MBARRIER_INIT(mbar, count) \
    asm volatile("mbarrier.init.shared.b64 [%0], %1;" :: "r"((uint32_t)(mbar)), "r"((uint32_t)(count)) : "memory")
#define MBARRIER_EXPECT_TX(mbar, bytes) \
    asm volatile("mbarrier.arrive.expect_tx.shared.b64 _, [%0], %1;" :: "r"((uint32_t)(mbar)), "r"((uint32_t)(bytes)) : "memory")
#define MBARRIER_WAIT_PARITY(mbar, parity) do { \
    uint32_t _m = (uint32_t)(mbar); uint32_t _p = (uint32_t)(parity); uint32_t _d; \
    asm volatile("{\n\t.reg .pred p;\n\t" \
        "mbarrier.try_wait.parity.acquire.cta.shared::cta.b64 p, [%1], %2;\n\t" \
        "selp.b32 %0, 1, 0, p;\n\t}" : "=r"(_d) : "r"(_m), "r"(_p) : "memory"); \
    if (!_d) { \
        asm volatile("{\n\t.reg .pred P1;\n\t" \
            "WL_%=:\n\t" \
            "mbarrier.try_wait.parity.acquire.cta.shared::cta.b64 P1, [%0], %1, 0x989680;\n\t" \
            "@P1 bra.uni WD_%=;\n\t" \
            "bra.uni WL_%=;\n\t" \
            "WD_%=:\n\t}" :: "r"(_m), "r"(_p) : "memory"); \
    } \
} while (0)

__device__ __forceinline__ void bulk_copy(uint32_t dst_smem, const void* src, uint32_t bytes,
                                          uint32_t mbar) {
    asm volatile("cp.async.bulk.shared::cta.global.mbarrier::complete_tx::bytes [%0], [%1], %2, [%3];"
                 :: "r"(dst_smem), "l"(src), "r"(bytes), "r"(mbar) : "memory");
}
__device__ __forceinline__ void ldsm4(uint32_t* r, uint32_t addr) {
    asm volatile("ldmatrix.sync.aligned.m8n8.x4.shared.b16 {%0,%1,%2,%3}, [%4];"
                 : "=r"(r[0]), "=r"(r[1]), "=r"(r[2]), "=r"(r[3]) : "r"(addr));
}
__device__ __forceinline__ void mma16816(float* d, const uint32_t* a, uint32_t b0, uint32_t b1) {
    asm volatile("mma.sync.aligned.m16n8k16.row.col.f32.bf16.bf16.f32 "
                 "{%0,%1,%2,%3}, {%4,%5,%6,%7}, {%8,%9}, {%0,%1,%2,%3};"
                 : "+f"(d[0]), "+f"(d[1]), "+f"(d[2]), "+f"(d[3])
                 : "r"(a[0]), "r"(a[1]), "r"(a[2]), "r"(a[3]), "r"(b0), "r"(b1));
}

// ---------------------------------------------------------------------------
// Kernel A: L2-normalize, scale (A side by 1/(T*ln2)), bf16-pack.
// which=0: A swizzled-row layout. which=1: B fragment layout.
// One warp per row; lane owns k = lane*8 .. lane*8+7.
// ---------------------------------------------------------------------------
__global__ void __launch_bounds__(256) norm_pack_kernel(const float* __restrict__ in, int which) {
    char* outB = (char*)(which ? g_fgB : g_flB);
    const float extra = which ? 1.0f : (float)(1.0 / (0.07 * 0.6931471805599453));
    const int wid = threadIdx.x >> 5;
    const int lane = threadIdx.x & 31;
    const int row = blockIdx.x * 8 + wid;

    const float4* r4 = (const float4*)(in + (size_t)row * DD);
    float4 a = r4[2 * lane];
    float4 b = r4[2 * lane + 1];

    float ss = a.x * a.x + a.y * a.y + a.z * a.z + a.w * a.w
             + b.x * b.x + b.y * b.y + b.z * b.z + b.w * b.w;
    #pragma unroll
    for (int off = 16; off > 0; off >>= 1)
        ss += __shfl_xor_sync(0xffffffffu, ss, off);
    float s = extra / fmaxf(sqrtf(ss), 1e-12f);

    __nv_bfloat162 h0 = __floats2bfloat162_rn(a.x * s, a.y * s);
    __nv_bfloat162 h1 = __floats2bfloat162_rn(a.z * s, a.w * s);
    __nv_bfloat162 h2 = __floats2bfloat162_rn(b.x * s, b.y * s);
    __nv_bfloat162 h3 = __floats2bfloat162_rn(b.z * s, b.w * s);
    uint32_t hv[4] = {*(uint32_t*)&h0, *(uint32_t*)&h1, *(uint32_t*)&h2, *(uint32_t*)&h3};

    const int t = row >> 7;            // tile
    char* tbase = outB + (size_t)t * TILE_BYTES;

    if (!which) {
        const int r = row & 127;
        const uint32_t off = (uint32_t)r * 512u + (uint32_t)((lane ^ (r & 7)) << 4);
        uint4 packed; packed.x = hv[0]; packed.y = hv[1]; packed.z = hv[2]; packed.w = hv[3];
        *(uint4*)(tbase + off) = packed;
    } else {
        // B fragment layout. This row is column n; lane holds k pairs p=4*lane+j.
        const int nl = row & 127;
        const int nf2 = nl >> 4;
        const int gl = nl & 15;
        const int g = gl & 7;
        const int ghi = gl >> 3;
        const int ks = lane >> 1;
        const int hi = lane & 1;
        char* blk = tbase + (uint32_t)(nf2 * 16 + ks) * 512u;
        #pragma unroll
        for (int j = 0; j < 4; j++)
            *(uint32_t*)(blk + (uint32_t)((g * 4 + j) * 16 + (ghi * 2 + hi) * 4)) = hv[j];
    }
}

// ---------------------------------------------------------------------------
__global__ void zero_bsum_kernel() {
    g_bsum[threadIdx.x] = 0.0f;
}

// ---------------------------------------------------------------------------
// Kernel B: HMMA GEMM + fused LSE. 16 warps all process the SAME tile i
// (warp tile 32x32: wm=w>>2 rows, wn=w&3 cols) so the B tile stays L1-resident.
// Previous tile's accumulators (accP) get their exp() spread across the current
// tile's k-loop (deferred epilogue) so MUFU overlaps the tensor pipe.
// ---------------------------------------------------------------------------
__global__ void __launch_bounds__(THREADS, 1) gemm_lse_kernel() {
    extern __shared__ __align__(128) char smem_raw[];
    const uint32_t sbase0 = smem_u32(smem_raw);
    const uint32_t cb = (sbase0 + 1023) & ~1023u;
    char* cptr = smem_raw + (cb - sbase0);

    const uint32_t MB_A = cb + 0;
    float* diag_s  = (float*)(cptr + 64);    // [128]
    float* red_s   = (float*)(cptr + 576);   // [128][4]
    float* sloss_s = (float*)(cptr + 2624);  // [128]
    const uint32_t A_S = cb + 4096;

    const int tid = threadIdx.x;
    const int lane = tid & 31;
    const int w = tid >> 5;
    const int wm = w >> 2;                   // M quarter (32 rows)
    const int wn = w & 3;                    // N quarter (32 cols)
    const int bx = blockIdx.x;

    if (tid == 0) MBARRIER_INIT(MB_A, 1);
    __syncthreads();
    if (tid == 0) {
        MBARRIER_EXPECT_TX(MB_A, TILE_BYTES);
        bulk_copy(A_S, (const char*)g_flB + (size_t)bx * TILE_BYTES, TILE_BYTES, MB_A);
    }

    // A ldmatrix addressing (swizzled 512B rows)
    const uint32_t xl = (uint32_t)(lane & 7);
    const int kbA = (lane >> 4) & 1;
    const int rbA = (lane >> 3) & 1;
    uint32_t aBase[2];
    #pragma unroll
    for (int mf = 0; mf < 2; mf++)
        aBase[mf] = A_S + (uint32_t)(wm * 32 + mf * 16 + (lane & 7) + rbA * 8) * 512u;

    const char* __restrict__ bAll = (const char*)g_fgB;
    const uint32_t bLane = (uint32_t)lane * 16u;
    const uint32_t bNfBase = (uint32_t)(wn * 2 * 16) * 512u;   // nf2 = wn*2 + q

    const int gq = lane >> 2;
    const int qq = lane & 3;

    float accP[2][4][4];
    #pragma unroll
    for (int mf = 0; mf < 2; mf++)
        #pragma unroll
        for (int nf = 0; nf < 4; nf++)
            #pragma unroll
            for (int c = 0; c < 4; c++) accP[mf][nf][c] = -1e30f;  // ex2 -> 0

    float rs[4] = {0.0f, 0.0f, 0.0f, 0.0f};

    MBARRIER_WAIT_PARITY(MB_A, 0);

    for (int i = 0; i < NTILES; i++) {
        const char* __restrict__ bW = bAll + (size_t)i * TILE_BYTES + bNfBase + bLane;

        if (i - 1 == bx) {   // diagonal lives in accP (tile i-1)
            #pragma unroll
            for (int mf = 0; mf < 2; mf++)
                #pragma unroll
                for (int q = 0; q < 2; q++)
                    #pragma unroll
                    for (int s8 = 0; s8 < 2; s8++)
                        #pragma unroll
                        for (int h = 0; h < 2; h++)
                            #pragma unroll
                            for (int cc = 0; cc < 2; cc++) {
                                int R = wm * 32 + mf * 16 + gq + h * 8;
                                int C = wn * 32 + q * 16 + s8 * 8 + qq * 2 + cc;
                                if (R == C) diag_s[R] = accP[mf][q * 2 + s8][h * 2 + cc];
                            }
        }

        float acc[2][4][4];
        #pragma unroll
        for (int mf = 0; mf < 2; mf++)
            #pragma unroll
            for (int nf = 0; nf < 4; nf++)
                #pragma unroll
                for (int c = 0; c < 4; c++) acc[mf][nf][c] = 0.0f;

        uint4 bf0[2], bf1[2];
        #pragma unroll
        for (int q = 0; q < 2; q++)
            bf0[q] = *(const uint4*)(bW + (uint32_t)(q * 16) * 512u);

        #pragma unroll
        for (int ks = 0; ks < 16; ks++) {
            uint4* cur = (ks & 1) ? bf1 : bf0;
            uint4* nxt = (ks & 1) ? bf0 : bf1;
            if (ks + 1 < 16) {
                #pragma unroll
                for (int q = 0; q < 2; q++)
                    nxt[q] = *(const uint4*)(bW + (uint32_t)(q * 16 + ks + 1) * 512u);
            }
            uint32_t afrag[2][4];
            const uint32_t cA = (uint32_t)((2 * ks + kbA) ^ (int)xl) << 4;
            #pragma unroll
            for (int mf = 0; mf < 2; mf++) ldsm4(afrag[mf], aBase[mf] + cA);
            #pragma unroll
            for (int mf = 0; mf < 2; mf++)
                #pragma unroll
                for (int q = 0; q < 2; q++) {
                    mma16816(acc[mf][q * 2],     afrag[mf], cur[q].x, cur[q].y);
                    mma16816(acc[mf][q * 2 + 1], afrag[mf], cur[q].z, cur[q].w);
                }
            // deferred epilogue: 2 elements of accP per ks (32 over 16 steps)
            {
                const int e  = 2 * ks;
                const int mf = e >> 4;
                const int nf = (e >> 2) & 3;
                const int c  = e & 3;             // 0 or 2
                rs[mf * 2 + (c >> 1)] += ex2f(accP[mf][nf][c]) + ex2f(accP[mf][nf][c + 1]);
            }
        }

        #pragma unroll
        for (int mf = 0; mf < 2; mf++)
            #pragma unroll
            for (int nf = 0; nf < 4; nf++)
                #pragma unroll
                for (int c = 0; c < 4; c++) accP[mf][nf][c] = acc[mf][nf][c];

        __syncthreads();   // keep all 16 warps on the same tile (L1 residency)
    }

    // drain tile 127 (held in accP)
    if (bx == NTILES - 1) {
        #pragma unroll
        for (int mf = 0; mf < 2; mf++)
            #pragma unroll
            for (int q = 0; q < 2; q++)
                #pragma unroll
                for (int s8 = 0; s8 < 2; s8++)
                    #pragma unroll
                    for (int h = 0; h < 2; h++)
                        #pragma unroll
                        for (int cc = 0; cc < 2; cc++) {
                            int R = wm * 32 + mf * 16 + gq + h * 8;
                            int C = wn * 32 + q * 16 + s8 * 8 + qq * 2 + cc;
                            if (R == C) diag_s[R] = accP[mf][q * 2 + s8][h * 2 + cc];
                        }
    }
    #pragma unroll
    for (int mf = 0; mf < 2; mf++)
        #pragma unroll
        for (int nf = 0; nf < 4; nf++)
            #pragma unroll
            for (int c = 0; c < 4; c += 2)
                rs[mf * 2 + (c >> 1)] += ex2f(accP[mf][nf][c]) + ex2f(accP[mf][nf][c + 1]);

    // lanes l, l^1, l^2 share the same rows
    #pragma unroll
    for (int j = 0; j < 4; j++) {
        rs[j] += __shfl_xor_sync(0xffffffffu, rs[j], 1);
        rs[j] += __shfl_xor_sync(0xffffffffu, rs[j], 2);
    }
    if ((lane & 3) == 0) {
        #pragma unroll
        for (int mf = 0; mf < 2; mf++)
            #pragma unroll
            for (int h = 0; h < 2; h++) {
                int R = wm * 32 + mf * 16 + gq + h * 8;
                red_s[R * 4 + wn] = rs[mf * 2 + h];
            }
    }
    __syncthreads();

    if (tid < 128) {
        const float tot = red_s[tid * 4] + red_s[tid * 4 + 1]
                        + red_s[tid * 4 + 2] + red_s[tid * 4 + 3];
        sloss_s[tid] = 0.6931471805599453f * (lg2f(tot) - diag_s[tid]);
    }
    __syncthreads();
    if (tid == 0) {
        float t = 0.0f;
        #pragma unroll 8
        for (int r = 0; r < BM; r++) t += sloss_s[r];
        g_bsum[bx] = t;
    }
}

// ---------------------------------------------------------------------------
__global__ void finalize_kernel(float* __restrict__ out) {
    __shared__ float sh[128];
    const int t = threadIdx.x;
    sh[t] = g_bsum[t];
    __syncthreads();
    #pragma unroll
    for (int off = 64; off > 0; off >>= 1) {
        if (t < off) sh[t] += sh[t + off];
        __syncthreads();
    }
    if (t == 0) out[0] = sh[0] / (float)NN;
}

// ---------------------------------------------------------------------------
extern "C" void kernel_launch(void* const* d_in, const int* in_sizes, int n_in,
                              void* d_out, int out_size) {
    const float* feat_local  = (const float*)d_in[0];
    const float* feat_global = (const float*)d_in[1];
    float* out = (float*)d_out;

    const int smem_bytes = 1024 + 4096 + TILE_BYTES;  // ~70.7 KB (A only)
    static bool attr_set = false;
    if (!attr_set) {
        cudaFuncSetAttribute(gemm_lse_kernel,
                             cudaFuncAttributeMaxDynamicSharedMemorySize, smem_bytes);
        attr_set = true;
    }

    norm_pack_kernel<<<NN / 8, 256>>>(feat_local, 0);   // launch 1
    norm_pack_kernel<<<NN / 8, 256>>>(feat_global, 1);  // launch 2
    zero_bsum_kernel<<<1, 128>>>();                     // launch 3
    gemm_lse_kernel<<<NN / BM, THREADS, smem_bytes>>>();// launch 4  <- profiled
    finalize_kernel<<<1, 128>>>(out);                   // launch 5
}

// round 15
// speedup vs baseline: 3.4196x; 1.4491x over previous
#include <cuda_runtime.h>
#include <cuda_bf16.h>
#include <cstdint>

#define NN 16384
#define DD 256
#define BM 128
#define NTILES (NN / 128)             // 128
#define TILE_BYTES (BM * DD * 2)      // 65536 (bf16)
#define THREADS 512                   // 16 warps: 2 tile-groups of 8

// A: per 128-row tile, row-major 512B rows with 16B-chunk XOR swizzle (ldmatrix).
// B: per 128-col tile, MMA-fragment order: 128 blocks of 512B, block = (nf2*16+ks).
__device__ __align__(128) __nv_bfloat16 g_flB[NN * DD];  // 8 MB, pre-scaled by 1/(T*ln2)
__device__ __align__(128) __nv_bfloat16 g_fgB[NN * DD];  // 8 MB
__device__ float g_bsum[NN / BM];

// ---------------------------------------------------------------------------
__device__ __forceinline__ uint32_t smem_u32(const void* p) {
    uint32_t a;
    asm("{ .reg .u64 t; cvta.to.shared.u64 t, %1; cvt.u32.u64 %0, t; }" : "=r"(a) : "l"(p));
    return a;
}
__device__ __forceinline__ float ex2f(float x) {
    float y; asm("ex2.approx.ftz.f32 %0, %1;" : "=f"(y) : "f"(x)); return y;
}
__device__ __forceinline__ float lg2f(float x) {
    float y; asm("lg2.approx.ftz.f32 %0, %1;" : "=f"(y) : "f"(x)); return y;
}

#define MBARRIER_INIT(mbar, count) \
    asm volatile("mbarrier.init.shared.b64 [%0], %1;" :: "r"((uint32_t)(mbar)), "r"((uint32_t)(count)) : "memory")
#define MBARRIER_EXPECT_TX(mbar, bytes) \
    asm volatile("mbarrier.arrive.expect_tx.shared.b64 _, [%0], %1;" :: "r"((uint32_t)(mbar)), "r"((uint32_t)(bytes)) : "memory")
#define MBARRIER_WAIT_PARITY(mbar, parity) do { \
    uint32_t _m = (uint32_t)(mbar); uint32_t _p = (uint32_t)(parity); uint32_t _d; \
    asm volatile("{\n\t.reg .pred p;\n\t" \
        "mbarrier.try_wait.parity.acquire.cta.shared::cta.b64 p, [%1], %2;\n\t" \
        "selp.b32 %0, 1, 0, p;\n\t}" : "=r"(_d) : "r"(_m), "r"(_p) : "memory"); \
    if (!_d) { \
        asm volatile("{\n\t.reg .pred P1;\n\t" \
            "WL_%=:\n\t" \
            "mbarrier.try_wait.parity.acquire.cta.shared::cta.b64 P1, [%0], %1, 0x989680;\n\t" \
            "@P1 bra.uni WD_%=;\n\t" \
            "bra.uni WL_%=;\n\t" \
            "WD_%=:\n\t}" :: "r"(_m), "r"(_p) : "memory"); \
    } \
} while (0)

__device__ __forceinline__ void bulk_copy(uint32_t dst_smem, const void* src, uint32_t bytes,
                                          uint32_t mbar) {
    asm volatile("cp.async.bulk.shared::cta.global.mbarrier::complete_tx::bytes [%0], [%1], %2, [%3];"
                 :: "r"(dst_smem), "l"(src), "r"(bytes), "r"(mbar) : "memory");
}
__device__ __forceinline__ void ldsm4(uint32_t* r, uint32_t addr) {
    asm volatile("ldmatrix.sync.aligned.m8n8.x4.shared.b16 {%0,%1,%2,%3}, [%4];"
                 : "=r"(r[0]), "=r"(r[1]), "=r"(r[2]), "=r"(r[3]) : "r"(addr));
}
__device__ __forceinline__ void mma16816(float* d, const uint32_t* a, uint32_t b0, uint32_t b1) {
    asm volatile("mma.sync.aligned.m16n8k16.row.col.f32.bf16.bf16.f32 "
                 "{%0,%1,%2,%3}, {%4,%5,%6,%7}, {%8,%9}, {%0,%1,%2,%3};"
                 : "+f"(d[0]), "+f"(d[1]), "+f"(d[2]), "+f"(d[3])
                 : "r"(a[0]), "r"(a[1]), "r"(a[2]), "r"(a[3]), "r"(b0), "r"(b1));
}

// ---------------------------------------------------------------------------
// Kernel A: L2-normalize, scale (A side by 1/(T*ln2)), bf16-pack.
// which=0: A swizzled-row layout. which=1: B fragment layout.
// One warp per row; lane owns k = lane*8 .. lane*8+7.
// ---------------------------------------------------------------------------
__global__ void __launch_bounds__(256) norm_pack_kernel(const float* __restrict__ in, int which) {
    char* outB = (char*)(which ? g_fgB : g_flB);
    const float extra = which ? 1.0f : (float)(1.0 / (0.07 * 0.6931471805599453));
    const int wid = threadIdx.x >> 5;
    const int lane = threadIdx.x & 31;
    const int row = blockIdx.x * 8 + wid;

    const float4* r4 = (const float4*)(in + (size_t)row * DD);
    float4 a = r4[2 * lane];
    float4 b = r4[2 * lane + 1];

    float ss = a.x * a.x + a.y * a.y + a.z * a.z + a.w * a.w
             + b.x * b.x + b.y * b.y + b.z * b.z + b.w * b.w;
    #pragma unroll
    for (int off = 16; off > 0; off >>= 1)
        ss += __shfl_xor_sync(0xffffffffu, ss, off);
    float s = extra / fmaxf(sqrtf(ss), 1e-12f);

    __nv_bfloat162 h0 = __floats2bfloat162_rn(a.x * s, a.y * s);
    __nv_bfloat162 h1 = __floats2bfloat162_rn(a.z * s, a.w * s);
    __nv_bfloat162 h2 = __floats2bfloat162_rn(b.x * s, b.y * s);
    __nv_bfloat162 h3 = __floats2bfloat162_rn(b.z * s, b.w * s);
    uint32_t hv[4] = {*(uint32_t*)&h0, *(uint32_t*)&h1, *(uint32_t*)&h2, *(uint32_t*)&h3};

    const int t = row >> 7;            // tile
    char* tbase = outB + (size_t)t * TILE_BYTES;

    if (!which) {
        const int r = row & 127;
        const uint32_t off = (uint32_t)r * 512u + (uint32_t)((lane ^ (r & 7)) << 4);
        uint4 packed; packed.x = hv[0]; packed.y = hv[1]; packed.z = hv[2]; packed.w = hv[3];
        *(uint4*)(tbase + off) = packed;
    } else {
        // B fragment layout. This row is column n; lane holds k pairs p=4*lane+j.
        const int nl = row & 127;
        const int nf2 = nl >> 4;
        const int gl = nl & 15;
        const int g = gl & 7;
        const int ghi = gl >> 3;
        const int ks = lane >> 1;
        const int hi = lane & 1;
        char* blk = tbase + (uint32_t)(nf2 * 16 + ks) * 512u;
        #pragma unroll
        for (int j = 0; j < 4; j++)
            *(uint32_t*)(blk + (uint32_t)((g * 4 + j) * 16 + (ghi * 2 + hi) * 4)) = hv[j];
    }
}

// ---------------------------------------------------------------------------
__global__ void zero_bsum_kernel() {
    g_bsum[threadIdx.x] = 0.0f;
}

// ---------------------------------------------------------------------------
// Kernel B: HMMA GEMM + fused LSE. 16 warps in 2 tile-groups of 8; group g
// sweeps full tiles i = 2j+g (barrier-free). Warp tile = 64x32 (acc 64 regs);
// within a group, 8 warps cover 2 M-halves x 4 N-quarters of the 128x128 tile.
// B working set = 2 tiles = 128 KB -> L1-resident.
// ---------------------------------------------------------------------------
__global__ void __launch_bounds__(THREADS, 1) gemm_lse_kernel() {
    extern __shared__ __align__(128) char smem_raw[];
    const uint32_t sbase0 = smem_u32(smem_raw);
    const uint32_t cb = (sbase0 + 1023) & ~1023u;
    char* cptr = smem_raw + (cb - sbase0);

    const uint32_t MB_A = cb + 0;
    float* diag_s  = (float*)(cptr + 64);    // [128]
    float* red_s   = (float*)(cptr + 576);   // [128][8]
    float* sloss_s = (float*)(cptr + 4672);  // [128]
    const uint32_t A_S = cb + 8192;

    const int tid = threadIdx.x;
    const int lane = tid & 31;
    const int w = tid >> 5;
    const int g = w >> 3;                    // tile-group 0/1
    const int wl = w & 7;
    const int wm = wl >> 2;                  // M half (64 rows)
    const int wn = wl & 3;                   // N quarter (32 cols)
    const int bx = blockIdx.x;

    if (tid == 0) MBARRIER_INIT(MB_A, 1);
    __syncthreads();
    if (tid == 0) {
        MBARRIER_EXPECT_TX(MB_A, TILE_BYTES);
        bulk_copy(A_S, (const char*)g_flB + (size_t)bx * TILE_BYTES, TILE_BYTES, MB_A);
    }

    // A ldmatrix addressing (swizzled 512B rows)
    const uint32_t xl = (uint32_t)(lane & 7);
    const int kbA = (lane >> 4) & 1;
    const int rbA = (lane >> 3) & 1;
    uint32_t aBase[4];
    #pragma unroll
    for (int mf = 0; mf < 4; mf++)
        aBase[mf] = A_S + (uint32_t)(wm * 64 + mf * 16 + (lane & 7) + rbA * 8) * 512u;

    const char* __restrict__ bAll = (const char*)g_fgB;
    const uint32_t bLane = (uint32_t)lane * 16u;
    const uint32_t bNfBase = (uint32_t)(wn * 2 * 16) * 512u;   // nf2 = wn*2 + q

    const int gq = lane >> 2;
    const int qq = lane & 3;

    float rs[8];
    #pragma unroll
    for (int j = 0; j < 8; j++) rs[j] = 0.0f;

    MBARRIER_WAIT_PARITY(MB_A, 0);

    for (int j = 0; j < NTILES / 2; j++) {
        const int i = 2 * j + g;             // this group's tile
        const char* __restrict__ bW = bAll + (size_t)i * TILE_BYTES + bNfBase + bLane;

        float acc[4][4][4];                  // [mf][q*2+s8][h*2+cc]
        #pragma unroll
        for (int mf = 0; mf < 4; mf++)
            #pragma unroll
            for (int nf = 0; nf < 4; nf++)
                #pragma unroll
                for (int c = 0; c < 4; c++) acc[mf][nf][c] = 0.0f;

        uint4 bf0[2], bf1[2];
        #pragma unroll
        for (int q = 0; q < 2; q++)
            bf0[q] = *(const uint4*)(bW + (uint32_t)(q * 16) * 512u);

        #pragma unroll
        for (int ks = 0; ks < 16; ks++) {
            uint4* cur = (ks & 1) ? bf1 : bf0;
            uint4* nxt = (ks & 1) ? bf0 : bf1;
            if (ks + 1 < 16) {
                #pragma unroll
                for (int q = 0; q < 2; q++)
                    nxt[q] = *(const uint4*)(bW + (uint32_t)(q * 16 + ks + 1) * 512u);
            }
            uint32_t afrag[4][4];
            const uint32_t cA = (uint32_t)((2 * ks + kbA) ^ (int)xl) << 4;
            #pragma unroll
            for (int mf = 0; mf < 4; mf++) ldsm4(afrag[mf], aBase[mf] + cA);
            #pragma unroll
            for (int mf = 0; mf < 4; mf++)
                #pragma unroll
                for (int q = 0; q < 2; q++) {
                    mma16816(acc[mf][q * 2],     afrag[mf], cur[q].x, cur[q].y);
                    mma16816(acc[mf][q * 2 + 1], afrag[mf], cur[q].z, cur[q].w);
                }
        }

        if (i == bx) {   // diagonal tile for this CTA (one group hits by parity)
            #pragma unroll
            for (int mf = 0; mf < 4; mf++)
                #pragma unroll
                for (int q = 0; q < 2; q++)
                    #pragma unroll
                    for (int s8 = 0; s8 < 2; s8++)
                        #pragma unroll
                        for (int h = 0; h < 2; h++)
                            #pragma unroll
                            for (int cc = 0; cc < 2; cc++) {
                                int R = wm * 64 + mf * 16 + gq + h * 8;
                                int C = wn * 32 + q * 16 + s8 * 8 + qq * 2 + cc;
                                if (R == C) diag_s[R] = acc[mf][q * 2 + s8][h * 2 + cc];
                            }
        }

        #pragma unroll
        for (int mf = 0; mf < 4; mf++)
            #pragma unroll
            for (int nf = 0; nf < 4; nf++) {
                rs[mf * 2 + 0] += ex2f(acc[mf][nf][0]) + ex2f(acc[mf][nf][1]);
                rs[mf * 2 + 1] += ex2f(acc[mf][nf][2]) + ex2f(acc[mf][nf][3]);
            }
    }

    // lanes l, l^1, l^2 share the same rows
    #pragma unroll
    for (int j = 0; j < 8; j++) {
        rs[j] += __shfl_xor_sync(0xffffffffu, rs[j], 1);
        rs[j] += __shfl_xor_sync(0xffffffffu, rs[j], 2);
    }
    if ((lane & 3) == 0) {
        #pragma unroll
        for (int mf = 0; mf < 4; mf++)
            #pragma unroll
            for (int h = 0; h < 2; h++) {
                int R = wm * 64 + mf * 16 + gq + h * 8;
                red_s[R * 8 + g * 4 + wn] = rs[mf * 2 + h];
            }
    }
    __syncthreads();

    if (tid < 128) {
        float tot = 0.0f;
        #pragma unroll
        for (int c = 0; c < 8; c++) tot += red_s[tid * 8 + c];
        sloss_s[tid] = 0.6931471805599453f * (lg2f(tot) - diag_s[tid]);
    }
    __syncthreads();
    if (tid == 0) {
        float t = 0.0f;
        #pragma unroll 8
        for (int r = 0; r < BM; r++) t += sloss_s[r];
        g_bsum[bx] = t;
    }
}

// ---------------------------------------------------------------------------
__global__ void finalize_kernel(float* __restrict__ out) {
    __shared__ float sh[128];
    const int t = threadIdx.x;
    sh[t] = g_bsum[t];
    __syncthreads();
    #pragma unroll
    for (int off = 64; off > 0; off >>= 1) {
        if (t < off) sh[t] += sh[t + off];
        __syncthreads();
    }
    if (t == 0) out[0] = sh[0] / (float)NN;
}

// ---------------------------------------------------------------------------
extern "C" void kernel_launch(void* const* d_in, const int* in_sizes, int n_in,
                              void* d_out, int out_size) {
    const float* feat_local  = (const float*)d_in[0];
    const float* feat_global = (const float*)d_in[1];
    float* out = (float*)d_out;

    const int smem_bytes = 1024 + 8192 + TILE_BYTES;  // ~73 KB (A only)
    static bool attr_set = false;
    if (!attr_set) {
        cudaFuncSetAttribute(gemm_lse_kernel,
                             cudaFuncAttributeMaxDynamicSharedMemorySize, smem_bytes);
        attr_set = true;
    }

    norm_pack_kernel<<<NN / 8, 256>>>(feat_local, 0);   // launch 1
    norm_pack_kernel<<<NN / 8, 256>>>(feat_global, 1);  // launch 2
    zero_bsum_kernel<<<1, 128>>>();                     // launch 3
    gemm_lse_kernel<<<NN / BM, THREADS, smem_bytes>>>();// launch 4  <- profiled
    finalize_kernel<<<1, 128>>>(out);                   // launch 5
}